// round 15
// baseline (speedup 1.0000x reference)
#include <cuda_runtime.h>
#include <cuda_fp16.h>
#include <stdint.h>

// ============================================================================
// Int8Linear — harness dtypes: x fp16->float32, w int8->int32, out fp16->float32.
//   out[m,n] = f32( fp16( fp32acc( x[m,:] . w[n,:] ) * scale[n] ) )
// M=8192, N=11008, K=4096.
// Round 15: R11 base (best: 1618us; fp16 W, 128x128, warp 64x32, 2 CTAs/SM,
// 3-stage cp.async) + (a) cp.async issue interleaved into compute substeps
// to smooth post-barrier LSU bursts, (b) fused single prep kernel.
// ============================================================================

namespace {

constexpr int GM = 8192;
constexpr int GN = 11008;
constexpr int GK = 4096;
constexpr int BM = 128;
constexpr int BN = 128;
constexpr int BK = 64;                    // 64 fp16 = 128B row (SW128 atom)
constexpr int KIT = GK / BK;              // 64
constexpr int NT = GN / BN;               // 86
constexpr int MT = GM / BM;               // 64
constexpr int STAGES = 3;
constexpr int TILE_B  = BM * 128;         // 16 KB
constexpr int STAGE_B = 2 * TILE_B;       // 32 KB
constexpr int SMEM_BYTES = 1024 + STAGES * STAGE_B;  // 99328 B (x2 CTAs fits)

constexpr int XBLOCKS = GM * GK / 8 / 256;   // 16384 (fp32->fp16, 8 elems/thr)
constexpr int WBLOCKS = GN * GK / 8 / 256;   // 22016 (int32->fp16, 8 elems/thr)

__device__ __align__(1024) __half g_xh[(size_t)GM * GK];   // 64 MB
__device__ __align__(1024) __half g_wh[(size_t)GN * GK];   // 90 MB

#define SW128(o) ((o) ^ (((o) >> 3) & 0x70u))

__device__ __forceinline__ uint32_t smem_u32(const void* p) {
    uint32_t a;
    asm("{ .reg .u64 t; cvta.to.shared.u64 t, %1; cvt.u32.u64 %0, t; }"
        : "=r"(a) : "l"(p));
    return a;
}

// exact packed-int8x4 -> 2x half2: ((b^0x80)|0x6400) - 1152
__device__ __forceinline__ void cvt4_i8_f16(uint32_t v, uint32_t* h2) {
    const uint32_t u = v ^ 0x80808080u;
    uint32_t lo = __byte_perm(u, 0x64646464u, 0x4140);
    uint32_t hi = __byte_perm(u, 0x64646464u, 0x4342);
    const uint32_t bias_u = 0x64806480u;  // half2(1152, 1152)
    __half2 a = __hsub2(*reinterpret_cast<const __half2*>(&lo),
                        *reinterpret_cast<const __half2*>(&bias_u));
    __half2 c = __hsub2(*reinterpret_cast<const __half2*>(&hi),
                        *reinterpret_cast<const __half2*>(&bias_u));
    h2[0] = *reinterpret_cast<uint32_t*>(&a);
    h2[1] = *reinterpret_cast<uint32_t*>(&c);
}

// ---------------------------------------------------------------------------
// fused prep: blocks [0, XBLOCKS) compact x (fp32->fp16);
//             blocks [XBLOCKS, XBLOCKS+WBLOCKS) compact w (int32->fp16 exact)
// ---------------------------------------------------------------------------
__global__ void __launch_bounds__(256)
prep_xw(const float* __restrict__ x, const int* __restrict__ w) {
    if (blockIdx.x < XBLOCKS) {
        const size_t e = ((size_t)blockIdx.x * 256 + threadIdx.x) * 8;
        float4 f0 = *reinterpret_cast<const float4*>(x + e);
        float4 f1 = *reinterpret_cast<const float4*>(x + e + 4);
        __half2 h0 = __floats2half2_rn(f0.x, f0.y);
        __half2 h1 = __floats2half2_rn(f0.z, f0.w);
        __half2 h2 = __floats2half2_rn(f1.x, f1.y);
        __half2 h3 = __floats2half2_rn(f1.z, f1.w);
        uint4 st;
        st.x = *reinterpret_cast<uint32_t*>(&h0);
        st.y = *reinterpret_cast<uint32_t*>(&h1);
        st.z = *reinterpret_cast<uint32_t*>(&h2);
        st.w = *reinterpret_cast<uint32_t*>(&h3);
        *reinterpret_cast<uint4*>(g_xh + e) = st;
    } else {
        const size_t e = ((size_t)(blockIdx.x - XBLOCKS) * 256 + threadIdx.x) * 8;
        int4 w0 = *reinterpret_cast<const int4*>(w + e);
        int4 w1 = *reinterpret_cast<const int4*>(w + e + 4);
        uint32_t t0 = __byte_perm((uint32_t)w0.x, (uint32_t)w0.y, 0x0040);
        uint32_t u0 = __byte_perm((uint32_t)w0.z, (uint32_t)w0.w, 0x0040);
        uint32_t r0 = __byte_perm(t0, u0, 0x5410);
        uint32_t t1 = __byte_perm((uint32_t)w1.x, (uint32_t)w1.y, 0x0040);
        uint32_t u1 = __byte_perm((uint32_t)w1.z, (uint32_t)w1.w, 0x0040);
        uint32_t r1 = __byte_perm(t1, u1, 0x5410);
        uint32_t h[4];
        cvt4_i8_f16(r0, h + 0);
        cvt4_i8_f16(r1, h + 2);
        *reinterpret_cast<uint4*>(g_wh + e) = make_uint4(h[0], h[1], h[2], h[3]);
    }
}

// ---------------------------------------------------------------------------
__device__ __forceinline__ void cpa16(uint32_t dst, const void* src) {
    asm volatile("cp.async.cg.shared.global [%0], [%1], 16;"
                 :: "r"(dst), "l"(src) : "memory");
}
__device__ __forceinline__ void cp_commit() {
    asm volatile("cp.async.commit_group;" ::: "memory");
}
template <int N>
__device__ __forceinline__ void cp_wait() {
    asm volatile("cp.async.wait_group %0;" :: "n"(N) : "memory");
}
__device__ __forceinline__ void ldsm4(uint32_t* r, uint32_t addr) {
    asm volatile("ldmatrix.sync.aligned.m8n8.x4.shared.b16 {%0,%1,%2,%3}, [%4];"
                 : "=r"(r[0]), "=r"(r[1]), "=r"(r[2]), "=r"(r[3]) : "r"(addr));
}
__device__ __forceinline__ void mma16816(float* c, const uint32_t* a,
                                         uint32_t b0, uint32_t b1) {
    asm volatile(
        "mma.sync.aligned.m16n8k16.row.col.f32.f16.f16.f32 "
        "{%0,%1,%2,%3}, {%4,%5,%6,%7}, {%8,%9}, {%0,%1,%2,%3};"
        : "+f"(c[0]), "+f"(c[1]), "+f"(c[2]), "+f"(c[3])
        : "r"(a[0]), "r"(a[1]), "r"(a[2]), "r"(a[3]), "r"(b0), "r"(b1));
}

__global__ void __launch_bounds__(256, 2)
gemm_kernel(const float* __restrict__ scale, float* __restrict__ out) {
    extern __shared__ char smem[];
    const uint32_t raw   = smem_u32(smem);
    const uint32_t tiles = (raw + 1023u) & ~1023u;   // 1KB align for SW128

    const int tid  = threadIdx.x;
    const int lane = tid & 31;
    const int warp = tid >> 5;
    const int wm   = warp >> 2;   // 0..1  (64 m-rows each)
    const int wn   = warp & 3;    // 0..3  (32 n-cols each)
    const int n0   = blockIdx.x * BN;   // N fastest -> W image L2-resident
    const int m0   = blockIdx.y * BM;

    const __half* ag = g_xh + (size_t)m0 * GK;
    const __half* bg = g_wh + (size_t)n0 * GK;

    // full-stage issue (prologue only)
    auto issue_full = [&](int kn) {
        const int s  = kn % STAGES;
        const int k0 = kn * BK;
        const uint32_t ab = tiles + s * STAGE_B;
        const uint32_t bb = ab + TILE_B;
#pragma unroll
        for (int p = 0; p < 4; ++p) {
            const int u = tid + p * 256;
            const int row = u >> 3, c = u & 7;
            const uint32_t o = SW128((uint32_t)(row * 128 + c * 16));
            cpa16(ab + o, ag + (size_t)row * GK + k0 + c * 8);
        }
#pragma unroll
        for (int p = 0; p < 4; ++p) {
            const int u = tid + p * 256;
            const int row = u >> 3, c = u & 7;
            const uint32_t o = SW128((uint32_t)(row * 128 + c * 16));
            cpa16(bb + o, bg + (size_t)row * GK + k0 + c * 8);
        }
        cp_commit();
    };
    // split halves for in-loop interleaving
    auto issue_a = [&](int kn) {
        const int s  = kn % STAGES;
        const int k0 = kn * BK;
        const uint32_t ab = tiles + s * STAGE_B;
#pragma unroll
        for (int p = 0; p < 4; ++p) {
            const int u = tid + p * 256;
            const int row = u >> 3, c = u & 7;
            const uint32_t o = SW128((uint32_t)(row * 128 + c * 16));
            cpa16(ab + o, ag + (size_t)row * GK + k0 + c * 8);
        }
    };
    auto issue_w = [&](int kn) {
        const int s  = kn % STAGES;
        const int k0 = kn * BK;
        const uint32_t bb = tiles + s * STAGE_B + TILE_B;
#pragma unroll
        for (int p = 0; p < 4; ++p) {
            const int u = tid + p * 256;
            const int row = u >> 3, c = u & 7;
            const uint32_t o = SW128((uint32_t)(row * 128 + c * 16));
            cpa16(bb + o, bg + (size_t)row * GK + k0 + c * 8);
        }
    };

    issue_full(0); issue_full(1);

    float acc[4][4][4];
#pragma unroll
    for (int t = 0; t < 4; ++t)
#pragma unroll
        for (int j = 0; j < 4; ++j)
#pragma unroll
            for (int e = 0; e < 4; ++e) acc[t][j][e] = 0.f;

    // ldmatrix per-lane address components (halves)
    const int row_a = wm * 64 + (lane & 15);                      // + t*16
    const int ka    = (lane >> 4) << 3;
    const int row_b = wn * 32 + ((lane >> 4) << 3) + (lane & 7);  // + g*16
    const int kb    = ((lane >> 3) & 1) << 3;

    for (int it = 0; it < KIT; ++it) {
        const int s = it % STAGES;

        cp_wait<1>();          // stage `it` complete (one group outstanding)
        __syncthreads();       // visible CTA-wide; stage (it-1) fully read

        const int  kn   = it + 2;
        const bool live = kn < KIT;

        const uint32_t abase = tiles + s * STAGE_B;
        const uint32_t bbase = abase + TILE_B;

#pragma unroll
        for (int st = 0; st < 4; ++st) {           // 4 x k16 per BK=64
            const int k2 = st * 16;
            uint32_t a[4][4], b[2][4];
#pragma unroll
            for (int t = 0; t < 4; ++t) {
                const uint32_t o = (uint32_t)((row_a + t * 16) * 128 + (k2 + ka) * 2);
                ldsm4(a[t], abase + SW128(o));
            }
#pragma unroll
            for (int g = 0; g < 2; ++g) {
                const uint32_t o = (uint32_t)((row_b + g * 16) * 128 + (k2 + kb) * 2);
                ldsm4(b[g], bbase + SW128(o));
            }
#pragma unroll
            for (int t = 0; t < 4; ++t)
#pragma unroll
                for (int j = 0; j < 4; ++j) {
                    const int g = j >> 1, h = j & 1;
                    mma16816(acc[t][j], a[t], b[g][2 * h], b[g][2 * h + 1]);
                }

            // interleave next-stage loads under the MMAs (smooth LSU bursts)
            if (st == 0 && live) issue_a(kn);
            if (st == 1 && live) issue_w(kn);
            if (st == 2)         cp_commit();   // always: group-count invariant
        }
        // no trailing barrier: next iteration's wait+barrier orders reuse
    }

    // ---- epilogue: scale, fp16 round (match reference), fp32 store ----
    const int mrow = m0 + wm * 64 + (lane >> 2);
    const int ncol = n0 + wn * 32 + (lane & 3) * 2;
    float* og = out + (size_t)mrow * GN + ncol;
    const float* scp = scale + ncol;

#pragma unroll
    for (int t = 0; t < 4; ++t) {
#pragma unroll
        for (int j = 0; j < 4; ++j) {
            const float2 sc = *reinterpret_cast<const float2*>(scp + j * 8);
            float2 r0, r1;
            r0.x = __half2float(__float2half_rn(acc[t][j][0] * sc.x));
            r0.y = __half2float(__float2half_rn(acc[t][j][1] * sc.y));
            r1.x = __half2float(__float2half_rn(acc[t][j][2] * sc.x));
            r1.y = __half2float(__float2half_rn(acc[t][j][3] * sc.y));
            *reinterpret_cast<float2*>(og + (size_t)(t * 16) * GN + j * 8)     = r0;
            *reinterpret_cast<float2*>(og + (size_t)(t * 16 + 8) * GN + j * 8) = r1;
        }
    }
}

}  // namespace

extern "C" void kernel_launch(void* const* d_in, const int* in_sizes, int n_in,
                              void* d_out, int out_size) {
    const float* x     = (const float*)d_in[0];
    const int*   w     = (const int*)d_in[1];
    const float* scale = (const float*)d_in[2];
    float*       out   = (float*)d_out;

    cudaFuncSetAttribute(gemm_kernel,
                         cudaFuncAttributeMaxDynamicSharedMemorySize, SMEM_BYTES);

    prep_xw<<<XBLOCKS + WBLOCKS, 256>>>(x, (const int*)w);   // 38400 blocks
    gemm_kernel<<<dim3(NT, MT), 256, SMEM_BYTES>>>(scale, out);
}

// round 16
// speedup vs baseline: 1.5325x; 1.5325x over previous
#include <cuda_runtime.h>
#include <cuda_fp16.h>
#include <stdint.h>

// ============================================================================
// Int8Linear — harness dtypes: x fp16->float32, w int8->int32, out fp16->float32.
//   out[m,n] = f32( fp16( fp32acc( x[m,:] . w[n,:] ) * scale[n] ) )
// M=8192, N=11008, K=4096.
// Round 15: R11 base (best: 1618us; fp16 W, 128x128, warp 64x32, 2 CTAs/SM,
// 3-stage cp.async) + (a) cp.async issue interleaved into compute substeps
// to smooth post-barrier LSU bursts, (b) fused single prep kernel.
// ============================================================================

namespace {

constexpr int GM = 8192;
constexpr int GN = 11008;
constexpr int GK = 4096;
constexpr int BM = 128;
constexpr int BN = 128;
constexpr int BK = 64;                    // 64 fp16 = 128B row (SW128 atom)
constexpr int KIT = GK / BK;              // 64
constexpr int NT = GN / BN;               // 86
constexpr int MT = GM / BM;               // 64
constexpr int STAGES = 3;
constexpr int TILE_B  = BM * 128;         // 16 KB
constexpr int STAGE_B = 2 * TILE_B;       // 32 KB
constexpr int SMEM_BYTES = 1024 + STAGES * STAGE_B;  // 99328 B (x2 CTAs fits)

constexpr int XBLOCKS = GM * GK / 8 / 256;   // 16384 (fp32->fp16, 8 elems/thr)
constexpr int WBLOCKS = GN * GK / 8 / 256;   // 22016 (int32->fp16, 8 elems/thr)

__device__ __align__(1024) __half g_xh[(size_t)GM * GK];   // 64 MB
__device__ __align__(1024) __half g_wh[(size_t)GN * GK];   // 90 MB

#define SW128(o) ((o) ^ (((o) >> 3) & 0x70u))

__device__ __forceinline__ uint32_t smem_u32(const void* p) {
    uint32_t a;
    asm("{ .reg .u64 t; cvta.to.shared.u64 t, %1; cvt.u32.u64 %0, t; }"
        : "=r"(a) : "l"(p));
    return a;
}

// exact packed-int8x4 -> 2x half2: ((b^0x80)|0x6400) - 1152
__device__ __forceinline__ void cvt4_i8_f16(uint32_t v, uint32_t* h2) {
    const uint32_t u = v ^ 0x80808080u;
    uint32_t lo = __byte_perm(u, 0x64646464u, 0x4140);
    uint32_t hi = __byte_perm(u, 0x64646464u, 0x4342);
    const uint32_t bias_u = 0x64806480u;  // half2(1152, 1152)
    __half2 a = __hsub2(*reinterpret_cast<const __half2*>(&lo),
                        *reinterpret_cast<const __half2*>(&bias_u));
    __half2 c = __hsub2(*reinterpret_cast<const __half2*>(&hi),
                        *reinterpret_cast<const __half2*>(&bias_u));
    h2[0] = *reinterpret_cast<uint32_t*>(&a);
    h2[1] = *reinterpret_cast<uint32_t*>(&c);
}

// ---------------------------------------------------------------------------
// fused prep: blocks [0, XBLOCKS) compact x (fp32->fp16);
//             blocks [XBLOCKS, XBLOCKS+WBLOCKS) compact w (int32->fp16 exact)
// ---------------------------------------------------------------------------
__global__ void __launch_bounds__(256)
prep_xw(const float* __restrict__ x, const int* __restrict__ w) {
    if (blockIdx.x < XBLOCKS) {
        const size_t e = ((size_t)blockIdx.x * 256 + threadIdx.x) * 8;
        float4 f0 = *reinterpret_cast<const float4*>(x + e);
        float4 f1 = *reinterpret_cast<const float4*>(x + e + 4);
        __half2 h0 = __floats2half2_rn(f0.x, f0.y);
        __half2 h1 = __floats2half2_rn(f0.z, f0.w);
        __half2 h2 = __floats2half2_rn(f1.x, f1.y);
        __half2 h3 = __floats2half2_rn(f1.z, f1.w);
        uint4 st;
        st.x = *reinterpret_cast<uint32_t*>(&h0);
        st.y = *reinterpret_cast<uint32_t*>(&h1);
        st.z = *reinterpret_cast<uint32_t*>(&h2);
        st.w = *reinterpret_cast<uint32_t*>(&h3);
        *reinterpret_cast<uint4*>(g_xh + e) = st;
    } else {
        const size_t e = ((size_t)(blockIdx.x - XBLOCKS) * 256 + threadIdx.x) * 8;
        int4 w0 = *reinterpret_cast<const int4*>(w + e);
        int4 w1 = *reinterpret_cast<const int4*>(w + e + 4);
        uint32_t t0 = __byte_perm((uint32_t)w0.x, (uint32_t)w0.y, 0x0040);
        uint32_t u0 = __byte_perm((uint32_t)w0.z, (uint32_t)w0.w, 0x0040);
        uint32_t r0 = __byte_perm(t0, u0, 0x5410);
        uint32_t t1 = __byte_perm((uint32_t)w1.x, (uint32_t)w1.y, 0x0040);
        uint32_t u1 = __byte_perm((uint32_t)w1.z, (uint32_t)w1.w, 0x0040);
        uint32_t r1 = __byte_perm(t1, u1, 0x5410);
        uint32_t h[4];
        cvt4_i8_f16(r0, h + 0);
        cvt4_i8_f16(r1, h + 2);
        *reinterpret_cast<uint4*>(g_wh + e) = make_uint4(h[0], h[1], h[2], h[3]);
    }
}

// ---------------------------------------------------------------------------
__device__ __forceinline__ void cpa16(uint32_t dst, const void* src) {
    asm volatile("cp.async.cg.shared.global [%0], [%1], 16;"
                 :: "r"(dst), "l"(src) : "memory");
}
__device__ __forceinline__ void cp_commit() {
    asm volatile("cp.async.commit_group;" ::: "memory");
}
template <int N>
__device__ __forceinline__ void cp_wait() {
    asm volatile("cp.async.wait_group %0;" :: "n"(N) : "memory");
}
__device__ __forceinline__ void ldsm4(uint32_t* r, uint32_t addr) {
    asm volatile("ldmatrix.sync.aligned.m8n8.x4.shared.b16 {%0,%1,%2,%3}, [%4];"
                 : "=r"(r[0]), "=r"(r[1]), "=r"(r[2]), "=r"(r[3]) : "r"(addr));
}
__device__ __forceinline__ void mma16816(float* c, const uint32_t* a,
                                         uint32_t b0, uint32_t b1) {
    asm volatile(
        "mma.sync.aligned.m16n8k16.row.col.f32.f16.f16.f32 "
        "{%0,%1,%2,%3}, {%4,%5,%6,%7}, {%8,%9}, {%0,%1,%2,%3};"
        : "+f"(c[0]), "+f"(c[1]), "+f"(c[2]), "+f"(c[3])
        : "r"(a[0]), "r"(a[1]), "r"(a[2]), "r"(a[3]), "r"(b0), "r"(b1));
}

__global__ void __launch_bounds__(256, 2)
gemm_kernel(const float* __restrict__ scale, float* __restrict__ out) {
    extern __shared__ char smem[];
    const uint32_t raw   = smem_u32(smem);
    const uint32_t tiles = (raw + 1023u) & ~1023u;   // 1KB align for SW128

    const int tid  = threadIdx.x;
    const int lane = tid & 31;
    const int warp = tid >> 5;
    const int wm   = warp >> 2;   // 0..1  (64 m-rows each)
    const int wn   = warp & 3;    // 0..3  (32 n-cols each)
    const int n0   = blockIdx.x * BN;   // N fastest -> W image L2-resident
    const int m0   = blockIdx.y * BM;

    const __half* ag = g_xh + (size_t)m0 * GK;
    const __half* bg = g_wh + (size_t)n0 * GK;

    // full-stage issue (prologue only)
    auto issue_full = [&](int kn) {
        const int s  = kn % STAGES;
        const int k0 = kn * BK;
        const uint32_t ab = tiles + s * STAGE_B;
        const uint32_t bb = ab + TILE_B;
#pragma unroll
        for (int p = 0; p < 4; ++p) {
            const int u = tid + p * 256;
            const int row = u >> 3, c = u & 7;
            const uint32_t o = SW128((uint32_t)(row * 128 + c * 16));
            cpa16(ab + o, ag + (size_t)row * GK + k0 + c * 8);
        }
#pragma unroll
        for (int p = 0; p < 4; ++p) {
            const int u = tid + p * 256;
            const int row = u >> 3, c = u & 7;
            const uint32_t o = SW128((uint32_t)(row * 128 + c * 16));
            cpa16(bb + o, bg + (size_t)row * GK + k0 + c * 8);
        }
        cp_commit();
    };
    // split halves for in-loop interleaving
    auto issue_a = [&](int kn) {
        const int s  = kn % STAGES;
        const int k0 = kn * BK;
        const uint32_t ab = tiles + s * STAGE_B;
#pragma unroll
        for (int p = 0; p < 4; ++p) {
            const int u = tid + p * 256;
            const int row = u >> 3, c = u & 7;
            const uint32_t o = SW128((uint32_t)(row * 128 + c * 16));
            cpa16(ab + o, ag + (size_t)row * GK + k0 + c * 8);
        }
    };
    auto issue_w = [&](int kn) {
        const int s  = kn % STAGES;
        const int k0 = kn * BK;
        const uint32_t bb = tiles + s * STAGE_B + TILE_B;
#pragma unroll
        for (int p = 0; p < 4; ++p) {
            const int u = tid + p * 256;
            const int row = u >> 3, c = u & 7;
            const uint32_t o = SW128((uint32_t)(row * 128 + c * 16));
            cpa16(bb + o, bg + (size_t)row * GK + k0 + c * 8);
        }
    };

    issue_full(0); issue_full(1);

    float acc[4][4][4];
#pragma unroll
    for (int t = 0; t < 4; ++t)
#pragma unroll
        for (int j = 0; j < 4; ++j)
#pragma unroll
            for (int e = 0; e < 4; ++e) acc[t][j][e] = 0.f;

    // ldmatrix per-lane address components (halves)
    const int row_a = wm * 64 + (lane & 15);                      // + t*16
    const int ka    = (lane >> 4) << 3;
    const int row_b = wn * 32 + ((lane >> 4) << 3) + (lane & 7);  // + g*16
    const int kb    = ((lane >> 3) & 1) << 3;

    for (int it = 0; it < KIT; ++it) {
        const int s = it % STAGES;

        cp_wait<1>();          // stage `it` complete (one group outstanding)
        __syncthreads();       // visible CTA-wide; stage (it-1) fully read

        const int  kn   = it + 2;
        const bool live = kn < KIT;

        const uint32_t abase = tiles + s * STAGE_B;
        const uint32_t bbase = abase + TILE_B;

#pragma unroll
        for (int st = 0; st < 4; ++st) {           // 4 x k16 per BK=64
            const int k2 = st * 16;
            uint32_t a[4][4], b[2][4];
#pragma unroll
            for (int t = 0; t < 4; ++t) {
                const uint32_t o = (uint32_t)((row_a + t * 16) * 128 + (k2 + ka) * 2);
                ldsm4(a[t], abase + SW128(o));
            }
#pragma unroll
            for (int g = 0; g < 2; ++g) {
                const uint32_t o = (uint32_t)((row_b + g * 16) * 128 + (k2 + kb) * 2);
                ldsm4(b[g], bbase + SW128(o));
            }
#pragma unroll
            for (int t = 0; t < 4; ++t)
#pragma unroll
                for (int j = 0; j < 4; ++j) {
                    const int g = j >> 1, h = j & 1;
                    mma16816(acc[t][j], a[t], b[g][2 * h], b[g][2 * h + 1]);
                }

            // interleave next-stage loads under the MMAs (smooth LSU bursts)
            if (st == 0 && live) issue_a(kn);
            if (st == 1 && live) issue_w(kn);
            if (st == 2)         cp_commit();   // always: group-count invariant
        }
        // no trailing barrier: next iteration's wait+barrier orders reuse
    }

    // ---- epilogue: scale, fp16 round (match reference), fp32 store ----
    const int mrow = m0 + wm * 64 + (lane >> 2);
    const int ncol = n0 + wn * 32 + (lane & 3) * 2;
    float* og = out + (size_t)mrow * GN + ncol;
    const float* scp = scale + ncol;

#pragma unroll
    for (int t = 0; t < 4; ++t) {
#pragma unroll
        for (int j = 0; j < 4; ++j) {
            const float2 sc = *reinterpret_cast<const float2*>(scp + j * 8);
            float2 r0, r1;
            r0.x = __half2float(__float2half_rn(acc[t][j][0] * sc.x));
            r0.y = __half2float(__float2half_rn(acc[t][j][1] * sc.y));
            r1.x = __half2float(__float2half_rn(acc[t][j][2] * sc.x));
            r1.y = __half2float(__float2half_rn(acc[t][j][3] * sc.y));
            *reinterpret_cast<float2*>(og + (size_t)(t * 16) * GN + j * 8)     = r0;
            *reinterpret_cast<float2*>(og + (size_t)(t * 16 + 8) * GN + j * 8) = r1;
        }
    }
}

}  // namespace

extern "C" void kernel_launch(void* const* d_in, const int* in_sizes, int n_in,
                              void* d_out, int out_size) {
    const float* x     = (const float*)d_in[0];
    const int*   w     = (const int*)d_in[1];
    const float* scale = (const float*)d_in[2];
    float*       out   = (float*)d_out;

    cudaFuncSetAttribute(gemm_kernel,
                         cudaFuncAttributeMaxDynamicSharedMemorySize, SMEM_BYTES);

    prep_xw<<<XBLOCKS + WBLOCKS, 256>>>(x, (const int*)w);   // 38400 blocks
    gemm_kernel<<<dim3(NT, MT), 256, SMEM_BYTES>>>(scale, out);
}

// round 17
// speedup vs baseline: 1.5828x; 1.0328x over previous
#include <cuda_runtime.h>
#include <cuda_fp16.h>
#include <stdint.h>

// ============================================================================
// Int8Linear — harness dtypes: x fp16->float32, w int8->int32, out fp16->float32.
//   out[m,n] = f32( fp16( fp32acc( x[m,:] . w[n,:] ) * scale[n] ) )
// M=8192, N=11008, K=4096.
// Round 17: 4 warps/CTA with 64x64 warp tiles (A-fragment LDS duplication
// 4x -> 2x; crossbar per iter 128KB -> 96KB). CTA 128x128, 2 CTAs/SM,
// 3-stage cp.async interleaved into compute substeps, SW128, fused prep.
// ============================================================================

namespace {

constexpr int GM = 8192;
constexpr int GN = 11008;
constexpr int GK = 4096;
constexpr int BM = 128;
constexpr int BN = 128;
constexpr int BK = 64;                    // 64 fp16 = 128B row (SW128 atom)
constexpr int KIT = GK / BK;              // 64
constexpr int NT = GN / BN;               // 86
constexpr int MT = GM / BM;               // 64
constexpr int STAGES = 3;
constexpr int THREADS = 128;              // 4 warps, 64x64 warp tile
constexpr int TILE_B  = BM * 128;         // 16 KB
constexpr int STAGE_B = 2 * TILE_B;       // 32 KB
constexpr int SMEM_BYTES = 1024 + STAGES * STAGE_B;  // 99328 B (x2 CTAs fits)

constexpr int XBLOCKS = GM * GK / 8 / 256;   // 16384
constexpr int WBLOCKS = GN * GK / 8 / 256;   // 22016

__device__ __align__(1024) __half g_xh[(size_t)GM * GK];   // 64 MB
__device__ __align__(1024) __half g_wh[(size_t)GN * GK];   // 90 MB

#define SW128(o) ((o) ^ (((o) >> 3) & 0x70u))

__device__ __forceinline__ uint32_t smem_u32(const void* p) {
    uint32_t a;
    asm("{ .reg .u64 t; cvta.to.shared.u64 t, %1; cvt.u32.u64 %0, t; }"
        : "=r"(a) : "l"(p));
    return a;
}

// exact packed-int8x4 -> 2x half2: ((b^0x80)|0x6400) - 1152
__device__ __forceinline__ void cvt4_i8_f16(uint32_t v, uint32_t* h2) {
    const uint32_t u = v ^ 0x80808080u;
    uint32_t lo = __byte_perm(u, 0x64646464u, 0x4140);
    uint32_t hi = __byte_perm(u, 0x64646464u, 0x4342);
    const uint32_t bias_u = 0x64806480u;  // half2(1152, 1152)
    __half2 a = __hsub2(*reinterpret_cast<const __half2*>(&lo),
                        *reinterpret_cast<const __half2*>(&bias_u));
    __half2 c = __hsub2(*reinterpret_cast<const __half2*>(&hi),
                        *reinterpret_cast<const __half2*>(&bias_u));
    h2[0] = *reinterpret_cast<uint32_t*>(&a);
    h2[1] = *reinterpret_cast<uint32_t*>(&c);
}

// ---------------------------------------------------------------------------
// fused prep: blocks [0, XBLOCKS) compact x; [XBLOCKS, +WBLOCKS) compact w
// ---------------------------------------------------------------------------
__global__ void __launch_bounds__(256)
prep_xw(const float* __restrict__ x, const int* __restrict__ w) {
    if (blockIdx.x < XBLOCKS) {
        const size_t e = ((size_t)blockIdx.x * 256 + threadIdx.x) * 8;
        float4 f0 = *reinterpret_cast<const float4*>(x + e);
        float4 f1 = *reinterpret_cast<const float4*>(x + e + 4);
        __half2 h0 = __floats2half2_rn(f0.x, f0.y);
        __half2 h1 = __floats2half2_rn(f0.z, f0.w);
        __half2 h2 = __floats2half2_rn(f1.x, f1.y);
        __half2 h3 = __floats2half2_rn(f1.z, f1.w);
        uint4 st;
        st.x = *reinterpret_cast<uint32_t*>(&h0);
        st.y = *reinterpret_cast<uint32_t*>(&h1);
        st.z = *reinterpret_cast<uint32_t*>(&h2);
        st.w = *reinterpret_cast<uint32_t*>(&h3);
        *reinterpret_cast<uint4*>(g_xh + e) = st;
    } else {
        const size_t e = ((size_t)(blockIdx.x - XBLOCKS) * 256 + threadIdx.x) * 8;
        int4 w0 = *reinterpret_cast<const int4*>(w + e);
        int4 w1 = *reinterpret_cast<const int4*>(w + e + 4);
        uint32_t t0 = __byte_perm((uint32_t)w0.x, (uint32_t)w0.y, 0x0040);
        uint32_t u0 = __byte_perm((uint32_t)w0.z, (uint32_t)w0.w, 0x0040);
        uint32_t r0 = __byte_perm(t0, u0, 0x5410);
        uint32_t t1 = __byte_perm((uint32_t)w1.x, (uint32_t)w1.y, 0x0040);
        uint32_t u1 = __byte_perm((uint32_t)w1.z, (uint32_t)w1.w, 0x0040);
        uint32_t r1 = __byte_perm(t1, u1, 0x5410);
        uint32_t h[4];
        cvt4_i8_f16(r0, h + 0);
        cvt4_i8_f16(r1, h + 2);
        *reinterpret_cast<uint4*>(g_wh + e) = make_uint4(h[0], h[1], h[2], h[3]);
    }
}

// ---------------------------------------------------------------------------
__device__ __forceinline__ void cpa16(uint32_t dst, const void* src) {
    asm volatile("cp.async.cg.shared.global [%0], [%1], 16;"
                 :: "r"(dst), "l"(src) : "memory");
}
__device__ __forceinline__ void cp_commit() {
    asm volatile("cp.async.commit_group;" ::: "memory");
}
template <int N>
__device__ __forceinline__ void cp_wait() {
    asm volatile("cp.async.wait_group %0;" :: "n"(N) : "memory");
}
__device__ __forceinline__ void ldsm4(uint32_t* r, uint32_t addr) {
    asm volatile("ldmatrix.sync.aligned.m8n8.x4.shared.b16 {%0,%1,%2,%3}, [%4];"
                 : "=r"(r[0]), "=r"(r[1]), "=r"(r[2]), "=r"(r[3]) : "r"(addr));
}
__device__ __forceinline__ void mma16816(float* c, const uint32_t* a,
                                         uint32_t b0, uint32_t b1) {
    asm volatile(
        "mma.sync.aligned.m16n8k16.row.col.f32.f16.f16.f32 "
        "{%0,%1,%2,%3}, {%4,%5,%6,%7}, {%8,%9}, {%0,%1,%2,%3};"
        : "+f"(c[0]), "+f"(c[1]), "+f"(c[2]), "+f"(c[3])
        : "r"(a[0]), "r"(a[1]), "r"(a[2]), "r"(a[3]), "r"(b0), "r"(b1));
}

__global__ void __launch_bounds__(THREADS, 2)
gemm_kernel(const float* __restrict__ scale, float* __restrict__ out) {
    extern __shared__ char smem[];
    const uint32_t raw   = smem_u32(smem);
    const uint32_t tiles = (raw + 1023u) & ~1023u;   // 1KB align for SW128

    const int tid  = threadIdx.x;
    const int lane = tid & 31;
    const int warp = tid >> 5;
    const int wm   = warp >> 1;   // 0..1  (64 m-rows each)
    const int wn   = warp & 1;    // 0..1  (64 n-cols each)
    const int n0   = blockIdx.x * BN;   // N fastest -> W image L2-resident
    const int m0   = blockIdx.y * BM;

    const __half* ag = g_xh + (size_t)m0 * GK;
    const __half* bg = g_wh + (size_t)n0 * GK;

    // A and W tiles: 1024 16B-units each; 128 threads -> 8 units/thread each
    auto issue_a = [&](int kn) {
        const int s  = kn % STAGES;
        const int k0 = kn * BK;
        const uint32_t ab = tiles + s * STAGE_B;
#pragma unroll
        for (int p = 0; p < 8; ++p) {
            const int u = tid + p * THREADS;
            const int row = u >> 3, c = u & 7;
            const uint32_t o = SW128((uint32_t)(row * 128 + c * 16));
            cpa16(ab + o, ag + (size_t)row * GK + k0 + c * 8);
        }
    };
    auto issue_w = [&](int kn) {
        const int s  = kn % STAGES;
        const int k0 = kn * BK;
        const uint32_t bb = tiles + s * STAGE_B + TILE_B;
#pragma unroll
        for (int p = 0; p < 8; ++p) {
            const int u = tid + p * THREADS;
            const int row = u >> 3, c = u & 7;
            const uint32_t o = SW128((uint32_t)(row * 128 + c * 16));
            cpa16(bb + o, bg + (size_t)row * GK + k0 + c * 8);
        }
    };

    issue_a(0); issue_w(0); cp_commit();
    issue_a(1); issue_w(1); cp_commit();

    float acc[4][8][4];
#pragma unroll
    for (int t = 0; t < 4; ++t)
#pragma unroll
        for (int j = 0; j < 8; ++j)
#pragma unroll
            for (int e = 0; e < 4; ++e) acc[t][j][e] = 0.f;

    // ldmatrix per-lane address components (halves)
    const int row_a = wm * 64 + (lane & 15);                      // + t*16
    const int ka    = (lane >> 4) << 3;
    const int row_b = wn * 64 + ((lane >> 4) << 3) + (lane & 7);  // + g*16
    const int kb    = ((lane >> 3) & 1) << 3;

    for (int it = 0; it < KIT; ++it) {
        const int s = it % STAGES;

        cp_wait<1>();          // stage `it` complete (one group outstanding)
        __syncthreads();       // visible CTA-wide; stage (it-1) fully read

        const int  kn   = it + 2;
        const bool live = kn < KIT;

        const uint32_t abase = tiles + s * STAGE_B;
        const uint32_t bbase = abase + TILE_B;

#pragma unroll
        for (int st = 0; st < 4; ++st) {           // 4 x k16 per BK=64
            const int k2 = st * 16;
            uint32_t a[4][4], b[4][4];
#pragma unroll
            for (int t = 0; t < 4; ++t) {
                const uint32_t o = (uint32_t)((row_a + t * 16) * 128 + (k2 + ka) * 2);
                ldsm4(a[t], abase + SW128(o));
            }
#pragma unroll
            for (int g = 0; g < 4; ++g) {
                const uint32_t o = (uint32_t)((row_b + g * 16) * 128 + (k2 + kb) * 2);
                ldsm4(b[g], bbase + SW128(o));
            }
#pragma unroll
            for (int t = 0; t < 4; ++t)
#pragma unroll
                for (int j = 0; j < 8; ++j) {
                    const int g = j >> 1, h = j & 1;
                    mma16816(acc[t][j], a[t], b[g][2 * h], b[g][2 * h + 1]);
                }

            // interleave next-stage loads under the MMAs (smooth LSU bursts)
            if (st == 0 && live) issue_a(kn);
            if (st == 1 && live) issue_w(kn);
            if (st == 2)         cp_commit();   // always: group-count invariant
        }
        // no trailing barrier: next iteration's wait+barrier orders reuse
    }

    // ---- epilogue: scale, fp16 round (match reference), fp32 store ----
    const int mrow = m0 + wm * 64 + (lane >> 2);
    const int ncol = n0 + wn * 64 + (lane & 3) * 2;
    float* og = out + (size_t)mrow * GN + ncol;
    const float* scp = scale + ncol;

#pragma unroll
    for (int t = 0; t < 4; ++t) {
#pragma unroll
        for (int j = 0; j < 8; ++j) {
            const float2 sc = *reinterpret_cast<const float2*>(scp + j * 8);
            float2 r0, r1;
            r0.x = __half2float(__float2half_rn(acc[t][j][0] * sc.x));
            r0.y = __half2float(__float2half_rn(acc[t][j][1] * sc.y));
            r1.x = __half2float(__float2half_rn(acc[t][j][2] * sc.x));
            r1.y = __half2float(__float2half_rn(acc[t][j][3] * sc.y));
            *reinterpret_cast<float2*>(og + (size_t)(t * 16) * GN + j * 8)     = r0;
            *reinterpret_cast<float2*>(og + (size_t)(t * 16 + 8) * GN + j * 8) = r1;
        }
    }
}

}  // namespace

extern "C" void kernel_launch(void* const* d_in, const int* in_sizes, int n_in,
                              void* d_out, int out_size) {
    const float* x     = (const float*)d_in[0];
    const int*   w     = (const int*)d_in[1];
    const float* scale = (const float*)d_in[2];
    float*       out   = (float*)d_out;

    cudaFuncSetAttribute(gemm_kernel,
                         cudaFuncAttributeMaxDynamicSharedMemorySize, SMEM_BYTES);

    prep_xw<<<XBLOCKS + WBLOCKS, 256>>>(x, (const int*)w);   // 38400 blocks
    gemm_kernel<<<dim3(NT, MT), THREADS, SMEM_BYTES>>>(scale, out);
}